// round 3
// baseline (speedup 1.0000x reference)
#include <cuda_runtime.h>
#include <cstdint>
#include <cstddef>

// ---------------------------------------------------------------------------
// Spiking conv + winner-takes-all, fused. Round 3: f32x2 packed accumulation.
//   One CTA per (b, ox, oy). 8 warps, each owns a 20-wide t-chunk.
//   Lane = jj*8+oq: jj = tau sub-phase (4 taus per LDG.128), oq = 4-channel grp.
// ---------------------------------------------------------------------------

#define COUT   32
#define W18    18          // C_IN * 3 * 3
#define KS     48
#define TIN    100
#define TOUT   149
#define NSPAT  31
#define THETA  5.4f
#define CHUNK  20

// resp table, layout [w18][tau][o]  (o innermost -> coalesced lane loads)
__device__ float g_resp[W18 * KS * COUT];

__global__ void resp_precompute(const float* __restrict__ weight) {
    int idx = blockIdx.x * blockDim.x + threadIdx.x;
    if (idx >= W18 * KS * COUT) return;
    int o   = idx & 31;
    int wt  = idx >> 5;          // w*48 + tau
    int tau = wt % KS;
    int w   = wt / KS;
    float wv = weight[o * W18 + w];
    float tf = (float)tau;
    float ts = tf * 0.0625f;                              // t/16
    float tl = -(tf - wv * 16.0f) * 0.03125f + wv;        // -(t-16w)/32 + w
    g_resp[idx] = fmaxf(0.0f, fminf(ts, tl));
}

// packed f32x2 add: a += v (component-wise, rn) — identical rounding to FADD
__device__ __forceinline__ void fadd2(unsigned long long& a, unsigned long long v) {
    asm("add.rn.f32x2 %0, %0, %1;" : "+l"(a) : "l"(v));
}

__global__ __launch_bounds__(256)
void wta_kernel(const float* __restrict__ xin, float* __restrict__ out) {
    __shared__ unsigned      s_bits[72];      // 18 rows x 4 words of spike bits
    __shared__ int4          s_spk4[456];     // 1824 packed spike entries
    __shared__ int           s_n;
    __shared__ unsigned char s_cand[160];     // per-t: winner if >THETA else 255
    __shared__ signed char   s_win[160];      // per-t: winner after refractory

    int* s_spk = (int*)s_spk4;

    const int tid  = threadIdx.x;
    const int lane = tid & 31;
    const int wp   = tid >> 5;                // 8 warps
    const int bx   = blockIdx.x;              // n = ox*31 + oy
    const int b    = blockIdx.y;
    const int ox   = bx / NSPAT;
    const int oy   = bx - ox * NSPAT;

    // ---- stage 1: build spike bitmasks (72 tasks = 18 rows x 4 words) ----
    float vv[9];
#pragma unroll
    for (int q = 0; q < 9; ++q) {
        int task = wp + q * 8;                // < 72
        int w    = task >> 2;
        int seg  = task & 3;
        int i    = w / 9;
        int rem  = w - i * 9;
        int kx   = rem / 3;
        int ky   = rem - kx * 3;
        int t    = seg * 32 + lane;
        const float* row = xin +
            ((((size_t)b * 2 + i) * 64 + (2 * ox + kx)) * 64 + (2 * oy + ky)) * TIN;
        vv[q] = (t < TIN) ? row[t] : 0.0f;
    }
#pragma unroll
    for (int q = 0; q < 9; ++q) {
        unsigned m = __ballot_sync(0xffffffffu, vv[q] != 0.0f);
        if (lane == 0) s_bits[wp + q * 8] = m;
    }
    __syncthreads();

    // ---- stage 2: deterministic compaction into spike list (warp 0) ----
    // entry = ((w*48 - s - 1 + 101) << 8) | s   (epart biased to 10 bits)
    if (wp == 0) {
        int cnt = 0;
        for (int base = 0; base < 72; base += 32) {
            int wi = base + lane;
            unsigned m = (wi < 72) ? s_bits[wi] : 0u;
            int c = __popc(m);
            int pre = c;
#pragma unroll
            for (int d = 1; d < 32; d <<= 1) {
                int v = __shfl_up_sync(0xffffffffu, pre, d);
                if (lane >= d) pre += v;
            }
            int off  = cnt + pre - c;
            int wrow = wi >> 2;
            int sb   = (wi & 3) << 5;
            while (m) {
                int bp = __ffs(m) - 1;
                m &= m - 1;
                int s = sb + bp;
                s_spk[off++] = ((wrow * KS - s - 1 + 101) << 8) | s;
            }
            cnt += __shfl_sync(0xffffffffu, pre, 31);
        }
        if (lane == 0) {
            s_n = cnt;
            int cpad = (cnt + 3) & ~3;
            for (int z = cnt; z < cpad; ++z) s_spk[z] = 255;  // s=255 -> skipped
        }
    }
    __syncthreads();

    // ---- stage 3: accumulate potentials (vectorized gather, f32x2 adds) ----
    const int jj = lane >> 3;                 // tau sub-phase 0..3
    const int oq = lane & 7;                  // channel quad 0..7
    const int t0 = wp * CHUNK;

    unsigned long long acc[5][2];
#pragma unroll
    for (int k2 = 0; k2 < 5; ++k2) { acc[k2][0] = 0ull; acc[k2][1] = 0ull; }

    const int nq = (s_n + 3) >> 2;
    const ulonglong2* tbl = (const ulonglong2*)g_resp + jj * 8 + oq;  // lane base

    for (int k4 = 0; k4 < nq; ++k4) {
        int4 e4 = s_spk4[k4];
        int ee[4] = {e4.x, e4.y, e4.z, e4.w};
#pragma unroll
        for (int q = 0; q < 4; ++q) {
            int e = ee[q];
            int s = e & 255;
            if ((unsigned)(s + KS - t0) <= 66u) {      // overlap with chunk
                int epart = (e >> 8) - 101;            // w*48 - s - 1
                int taub  = t0 - s - 1 + jj;           // tau of slot k2=0
                const ulonglong2* p = tbl + (epart + t0) * 8;
#pragma unroll
                for (int k2 = 0; k2 < 5; ++k2) {
                    if ((unsigned)(taub + 4 * k2) < (unsigned)KS) {
                        ulonglong2 v = p[32 * k2];     // LDG.128 (read-only global)
                        fadd2(acc[k2][0], v.x);
                        fadd2(acc[k2][1], v.y);
                    }
                }
            }
        }
    }

    // ---- stage 4: per-t argmax (float4 local, then 8-lane group reduce) ----
#pragma unroll
    for (int k2 = 0; k2 < 5; ++k2) {
        int t = t0 + 4 * k2 + jj;
        float ax = __uint_as_float((unsigned)(acc[k2][0] & 0xffffffffull));
        float ay = __uint_as_float((unsigned)(acc[k2][0] >> 32));
        float az = __uint_as_float((unsigned)(acc[k2][1] & 0xffffffffull));
        float aw = __uint_as_float((unsigned)(acc[k2][1] >> 32));
        float bv = ax;
        int   bi = oq * 4;
        if (ay > bv) { bv = ay; bi = oq * 4 + 1; }
        if (az > bv) { bv = az; bi = oq * 4 + 2; }
        if (aw > bv) { bv = aw; bi = oq * 4 + 3; }
#pragma unroll
        for (int off = 4; off > 0; off >>= 1) {
            float ov = __shfl_down_sync(0xffffffffu, bv, off, 8);
            int   oi = __shfl_down_sync(0xffffffffu, bi, off, 8);
            if (ov > bv) { bv = ov; bi = oi; }   // strict >: lower channel wins ties
        }
        if (oq == 0 && t < TOUT)
            s_cand[t] = (bv > THETA) ? (unsigned char)bi : (unsigned char)255;
    }
    __syncthreads();

    // ---- stage 5: sequential depression scan ----
    if (tid == 0) {
        int dep = 0;
#pragma unroll 1
        for (int t = 0; t < TOUT; ++t) {
            int c = s_cand[t];
            int winv = -1;
            if (dep == 0 && c != 255) { winv = c; dep = KS; }
            s_win[t] = (signed char)winv;
            dep = dep > 0 ? dep - 1 : 0;
        }
    }
    __syncthreads();

    // ---- stage 6: write output rows (coalesced, every element written) ----
#pragma unroll
    for (int r = 0; r < 4; ++r) {
        int oc = wp * 4 + r;
        float* orow = out + (((size_t)b * COUT + oc) * (NSPAT * NSPAT) + bx) * TOUT;
        for (int t = lane; t < TOUT; t += 32)
            orow[t] = ((int)s_win[t] == oc) ? 1.0f : 0.0f;
    }
}

extern "C" void kernel_launch(void* const* d_in, const int* in_sizes, int n_in,
                              void* d_out, int out_size) {
    const float* spikes = (const float*)d_in[0];
    const float* weight = (const float*)d_in[1];
    if (n_in >= 2 && in_sizes[0] == 576) {     // defensive input identification
        spikes = (const float*)d_in[1];
        weight = (const float*)d_in[0];
    }

    resp_precompute<<<(W18 * KS * COUT + 255) / 256, 256>>>(weight);

    dim3 grid(NSPAT * NSPAT, 16);   // (n, batch)
    wta_kernel<<<grid, 256>>>(spikes, (float*)d_out);
}

// round 4
// speedup vs baseline: 1.0005x; 1.0005x over previous
#include <cuda_runtime.h>
#include <cstdint>
#include <cstddef>

// ---------------------------------------------------------------------------
// Spiking conv + winner-takes-all, fused. Round 3: f32x2 packed accumulation.
//   One CTA per (b, ox, oy). 8 warps, each owns a 20-wide t-chunk.
//   Lane = jj*8+oq: jj = tau sub-phase (4 taus per LDG.128), oq = 4-channel grp.
// ---------------------------------------------------------------------------

#define COUT   32
#define W18    18          // C_IN * 3 * 3
#define KS     48
#define TIN    100
#define TOUT   149
#define NSPAT  31
#define THETA  5.4f
#define CHUNK  20

// resp table, layout [w18][tau][o]  (o innermost -> coalesced lane loads)
__device__ float g_resp[W18 * KS * COUT];

__global__ void resp_precompute(const float* __restrict__ weight) {
    int idx = blockIdx.x * blockDim.x + threadIdx.x;
    if (idx >= W18 * KS * COUT) return;
    int o   = idx & 31;
    int wt  = idx >> 5;          // w*48 + tau
    int tau = wt % KS;
    int w   = wt / KS;
    float wv = weight[o * W18 + w];
    float tf = (float)tau;
    float ts = tf * 0.0625f;                              // t/16
    float tl = -(tf - wv * 16.0f) * 0.03125f + wv;        // -(t-16w)/32 + w
    g_resp[idx] = fmaxf(0.0f, fminf(ts, tl));
}

// packed f32x2 add: a += v (component-wise, rn) — identical rounding to FADD
__device__ __forceinline__ void fadd2(unsigned long long& a, unsigned long long v) {
    asm("add.rn.f32x2 %0, %0, %1;" : "+l"(a) : "l"(v));
}

__global__ __launch_bounds__(256)
void wta_kernel(const float* __restrict__ xin, float* __restrict__ out) {
    __shared__ unsigned      s_bits[72];      // 18 rows x 4 words of spike bits
    __shared__ int4          s_spk4[456];     // 1824 packed spike entries
    __shared__ int           s_n;
    __shared__ unsigned char s_cand[160];     // per-t: winner if >THETA else 255
    __shared__ signed char   s_win[160];      // per-t: winner after refractory

    int* s_spk = (int*)s_spk4;

    const int tid  = threadIdx.x;
    const int lane = tid & 31;
    const int wp   = tid >> 5;                // 8 warps
    const int bx   = blockIdx.x;              // n = ox*31 + oy
    const int b    = blockIdx.y;
    const int ox   = bx / NSPAT;
    const int oy   = bx - ox * NSPAT;

    // ---- stage 1: build spike bitmasks (72 tasks = 18 rows x 4 words) ----
    float vv[9];
#pragma unroll
    for (int q = 0; q < 9; ++q) {
        int task = wp + q * 8;                // < 72
        int w    = task >> 2;
        int seg  = task & 3;
        int i    = w / 9;
        int rem  = w - i * 9;
        int kx   = rem / 3;
        int ky   = rem - kx * 3;
        int t    = seg * 32 + lane;
        const float* row = xin +
            ((((size_t)b * 2 + i) * 64 + (2 * ox + kx)) * 64 + (2 * oy + ky)) * TIN;
        vv[q] = (t < TIN) ? row[t] : 0.0f;
    }
#pragma unroll
    for (int q = 0; q < 9; ++q) {
        unsigned m = __ballot_sync(0xffffffffu, vv[q] != 0.0f);
        if (lane == 0) s_bits[wp + q * 8] = m;
    }
    __syncthreads();

    // ---- stage 2: deterministic compaction into spike list (warp 0) ----
    // entry = ((w*48 - s - 1 + 101) << 8) | s   (epart biased to 10 bits)
    if (wp == 0) {
        int cnt = 0;
        for (int base = 0; base < 72; base += 32) {
            int wi = base + lane;
            unsigned m = (wi < 72) ? s_bits[wi] : 0u;
            int c = __popc(m);
            int pre = c;
#pragma unroll
            for (int d = 1; d < 32; d <<= 1) {
                int v = __shfl_up_sync(0xffffffffu, pre, d);
                if (lane >= d) pre += v;
            }
            int off  = cnt + pre - c;
            int wrow = wi >> 2;
            int sb   = (wi & 3) << 5;
            while (m) {
                int bp = __ffs(m) - 1;
                m &= m - 1;
                int s = sb + bp;
                s_spk[off++] = ((wrow * KS - s - 1 + 101) << 8) | s;
            }
            cnt += __shfl_sync(0xffffffffu, pre, 31);
        }
        if (lane == 0) {
            s_n = cnt;
            int cpad = (cnt + 3) & ~3;
            for (int z = cnt; z < cpad; ++z) s_spk[z] = 255;  // s=255 -> skipped
        }
    }
    __syncthreads();

    // ---- stage 3: accumulate potentials (vectorized gather, f32x2 adds) ----
    const int jj = lane >> 3;                 // tau sub-phase 0..3
    const int oq = lane & 7;                  // channel quad 0..7
    const int t0 = wp * CHUNK;

    unsigned long long acc[5][2];
#pragma unroll
    for (int k2 = 0; k2 < 5; ++k2) { acc[k2][0] = 0ull; acc[k2][1] = 0ull; }

    const int nq = (s_n + 3) >> 2;
    const ulonglong2* tbl = (const ulonglong2*)g_resp + jj * 8 + oq;  // lane base

    for (int k4 = 0; k4 < nq; ++k4) {
        int4 e4 = s_spk4[k4];
        int ee[4] = {e4.x, e4.y, e4.z, e4.w};
#pragma unroll
        for (int q = 0; q < 4; ++q) {
            int e = ee[q];
            int s = e & 255;
            if ((unsigned)(s + KS - t0) <= 66u) {      // overlap with chunk
                int epart = (e >> 8) - 101;            // w*48 - s - 1
                int taub  = t0 - s - 1 + jj;           // tau of slot k2=0
                const ulonglong2* p = tbl + (epart + t0) * 8;
#pragma unroll
                for (int k2 = 0; k2 < 5; ++k2) {
                    if ((unsigned)(taub + 4 * k2) < (unsigned)KS) {
                        ulonglong2 v = p[32 * k2];     // LDG.128 (read-only global)
                        fadd2(acc[k2][0], v.x);
                        fadd2(acc[k2][1], v.y);
                    }
                }
            }
        }
    }

    // ---- stage 4: per-t argmax (float4 local, then 8-lane group reduce) ----
#pragma unroll
    for (int k2 = 0; k2 < 5; ++k2) {
        int t = t0 + 4 * k2 + jj;
        float ax = __uint_as_float((unsigned)(acc[k2][0] & 0xffffffffull));
        float ay = __uint_as_float((unsigned)(acc[k2][0] >> 32));
        float az = __uint_as_float((unsigned)(acc[k2][1] & 0xffffffffull));
        float aw = __uint_as_float((unsigned)(acc[k2][1] >> 32));
        float bv = ax;
        int   bi = oq * 4;
        if (ay > bv) { bv = ay; bi = oq * 4 + 1; }
        if (az > bv) { bv = az; bi = oq * 4 + 2; }
        if (aw > bv) { bv = aw; bi = oq * 4 + 3; }
#pragma unroll
        for (int off = 4; off > 0; off >>= 1) {
            float ov = __shfl_down_sync(0xffffffffu, bv, off, 8);
            int   oi = __shfl_down_sync(0xffffffffu, bi, off, 8);
            if (ov > bv) { bv = ov; bi = oi; }   // strict >: lower channel wins ties
        }
        if (oq == 0 && t < TOUT)
            s_cand[t] = (bv > THETA) ? (unsigned char)bi : (unsigned char)255;
    }
    __syncthreads();

    // ---- stage 5: sequential depression scan ----
    if (tid == 0) {
        int dep = 0;
#pragma unroll 1
        for (int t = 0; t < TOUT; ++t) {
            int c = s_cand[t];
            int winv = -1;
            if (dep == 0 && c != 255) { winv = c; dep = KS; }
            s_win[t] = (signed char)winv;
            dep = dep > 0 ? dep - 1 : 0;
        }
    }
    __syncthreads();

    // ---- stage 6: write output rows (coalesced, every element written) ----
#pragma unroll
    for (int r = 0; r < 4; ++r) {
        int oc = wp * 4 + r;
        float* orow = out + (((size_t)b * COUT + oc) * (NSPAT * NSPAT) + bx) * TOUT;
        for (int t = lane; t < TOUT; t += 32)
            orow[t] = ((int)s_win[t] == oc) ? 1.0f : 0.0f;
    }
}

extern "C" void kernel_launch(void* const* d_in, const int* in_sizes, int n_in,
                              void* d_out, int out_size) {
    const float* spikes = (const float*)d_in[0];
    const float* weight = (const float*)d_in[1];
    if (n_in >= 2 && in_sizes[0] == 576) {     // defensive input identification
        spikes = (const float*)d_in[1];
        weight = (const float*)d_in[0];
    }

    resp_precompute<<<(W18 * KS * COUT + 255) / 256, 256>>>(weight);

    dim3 grid(NSPAT * NSPAT, 16);   // (n, batch)
    wta_kernel<<<grid, 256>>>(spikes, (float*)d_out);
}

// round 5
// speedup vs baseline: 1.9215x; 1.9205x over previous
#include <cuda_runtime.h>
#include <cstdint>
#include <cstddef>

// ---------------------------------------------------------------------------
// Spiking conv + WTA, Round 5: exact relu-decomposition, delta^2 event scatter,
// double-cumsum reconstruction. One 32-thread CTA per (b,ox,oy); lane=channel.
//   r(tau) = tau/16 - (3/32) relu(tau-16w) + (1/32) relu(tau-48w)   (exact)
// Sampled second-difference: 1 shared ramp event + 2 events per hinge.
// ---------------------------------------------------------------------------

#define COUT   32
#define W18    18
#define KS     48
#define TIN    100
#define TOUT   149
#define NSPAT  31
#define THETA  5.4f
#define GROWS  152

// event tables, layout [w][o]
__device__ float4 g_t1[W18 * COUT];   // ev1a, ev1b, ev2a, ev2b
__device__ int    g_t2[W18 * COUT];   // n1 | (n2<<16)

__global__ void evt_precompute(const float* __restrict__ weight) {
    int idx = blockIdx.x * blockDim.x + threadIdx.x;
    if (idx >= W18 * COUT) return;
    int o = idx & 31;
    int w = idx >> 5;
    double wv = (double)weight[o * W18 + w];

    double p1 = 16.0 * wv;                    // peak knot
    int    n1 = (int)floor(p1) + 1;
    double f1 = (double)n1 - p1;              // in (0,1]
    const double c1 = -3.0 / 32.0;
    double p2 = 48.0 * wv;                    // zero-cross knot
    int    n2 = (int)floor(p2) + 1;
    double f2 = (double)n2 - p2;
    const double c2 = 1.0 / 32.0;

    g_t1[idx] = make_float4((float)(c1 * f1), (float)(c1 * (1.0 - f1)),
                            (float)(c2 * f2), (float)(c2 * (1.0 - f2)));
    g_t2[idx] = n1 | (n2 << 16);
}

// Neumaier compensated add: s += v, compensation c
__device__ __forceinline__ void kadd(float& s, float& c, float v) {
    float t = s + v;
    float e = (fabsf(s) >= fabsf(v)) ? ((s - t) + v) : ((v - t) + s);
    c += e;
    s = t;
}

__global__ __launch_bounds__(32)
void wta_kernel(const float* __restrict__ xin, float* __restrict__ out) {
    __shared__ float          s_grid[GROWS * COUT];  // d^2 grid, bank = lane
    __shared__ unsigned short s_spk[1824];           // (w<<7)|s
    __shared__ float          s_cnt[GROWS];          // shared-ramp d2 (count/16)
    __shared__ unsigned       s_bits[72];
    __shared__ int            s_win[GROWS];          // winner per t, -1 none

    const int lane = threadIdx.x;
    const int bx   = blockIdx.x;                     // n = ox*31 + oy
    const int b    = blockIdx.y;
    const int ox   = bx / NSPAT;
    const int oy   = bx - ox * NSPAT;

    // ---- zero grid / cnt / win ----
    {
        float4 z4 = make_float4(0.f, 0.f, 0.f, 0.f);
        float4* g4 = (float4*)s_grid;
#pragma unroll
        for (int i = lane; i < GROWS * COUT / 4; i += 32) g4[i] = z4;
#pragma unroll
        for (int i = lane; i < GROWS; i += 32) { s_cnt[i] = 0.f; s_win[i] = -1; }
    }

    // ---- stage 1: spike bitmasks (72 = 18 rows x 4 t-segments) ----
    float vbuf[24];
#pragma unroll
    for (int batch = 0; batch < 3; ++batch) {
#pragma unroll
        for (int j = 0; j < 24; ++j) {
            int task = batch * 24 + j;
            int w = task >> 2, seg = task & 3;
            int i = w / 9, rem = w - i * 9, kx = rem / 3, ky = rem - kx * 3;
            int t = seg * 32 + lane;
            const float* row = xin +
                ((((size_t)b * 2 + i) * 64 + (2 * ox + kx)) * 64 + (2 * oy + ky)) * TIN;
            vbuf[j] = (t < TIN) ? __ldg(row + t) : 0.f;
        }
#pragma unroll
        for (int j = 0; j < 24; ++j) {
            unsigned m = __ballot_sync(0xffffffffu, vbuf[j] != 0.f);
            if (lane == 0) s_bits[batch * 24 + j] = m;
        }
    }
    __syncwarp();

    // ---- stage 1b: shared-ramp counts: cnt[s+2] = (#spikes at s)/16 ----
#pragma unroll
    for (int seg = 0; seg < 4; ++seg) {
        int c = 0;
#pragma unroll
        for (int w = 0; w < 18; ++w) c += (int)((s_bits[w * 4 + seg] >> lane) & 1u);
        int s = seg * 32 + lane;
        if (s < TIN) s_cnt[s + 2] = (float)c * 0.0625f;
    }

    // ---- stage 2: compact spike list (deterministic order) ----
    int cnt = 0;
#pragma unroll
    for (int base = 0; base < 96; base += 32) {
        int wi = base + lane;
        unsigned m = (wi < 72) ? s_bits[wi] : 0u;
        int c = __popc(m);
        int pre = c;
#pragma unroll
        for (int d = 1; d < 32; d <<= 1) {
            int v = __shfl_up_sync(0xffffffffu, pre, d);
            if (lane >= d) pre += v;
        }
        int off  = cnt + pre - c;
        int wrow = wi >> 2;
        int sb   = (wi & 3) << 5;
        while (m) {
            int bp = __ffs((int)m) - 1;
            m &= m - 1;
            s_spk[off++] = (unsigned short)((wrow << 7) | (sb + bp));
        }
        cnt += __shfl_sync(0xffffffffu, pre, 31);
    }
    __syncwarp();

    // ---- stage 3: scatter hinge events (4 per spike, lane-private column) ----
    float* col = s_grid + lane;
#pragma unroll 2
    for (int k = 0; k < cnt; ++k) {
        int e = s_spk[k];
        int s = e & 127;
        int w = e >> 7;
        float4 ev = __ldg(&g_t1[w * 32 + lane]);
        int    nn = __ldg(&g_t2[w * 32 + lane]);
        int n1 = nn & 0xffff;
        int n2 = nn >> 16;
        int r  = s + 1;
        col[(r + n1)     * 32] += ev.x;
        col[(r + n1 + 1) * 32] += ev.y;
        col[(r + n2)     * 32] += ev.z;
        col[(r + n2 + 1) * 32] += ev.w;
    }
    __syncwarp();

    // ---- stage 4: double cumsum + WTA (sequential t, warp-uniform dep) ----
    {
        float a1 = 0.f, c1 = 0.f;    // slope (compensated)
        float a2 = 0.f;              // potential
        int dep = 0;
#pragma unroll 1
        for (int t = 0; t < TOUT; ++t) {
            kadd(a1, c1, s_grid[t * 32 + lane]);
            kadd(a1, c1, s_cnt[t]);
            a2 += (a1 + c1);
            if (dep == 0) {
                float bv = a2; int bi = lane;
#pragma unroll
                for (int off = 16; off; off >>= 1) {
                    float ov = __shfl_xor_sync(0xffffffffu, bv, off);
                    int   oi = __shfl_xor_sync(0xffffffffu, bi, off);
                    if (ov > bv || (ov == bv && oi < bi)) { bv = ov; bi = oi; }
                }
                if (bv > THETA) {
                    if (lane == 0) s_win[t] = bi;
                    dep = 48;
                }
            }
            dep = dep > 0 ? dep - 1 : 0;
        }
    }
    __syncwarp();

    // ---- stage 5: write output (coalesced, every element written) ----
#pragma unroll
    for (int q = 0; q < 5; ++q) {
        int t = q * 32 + lane;
        int wv = (t < TOUT) ? s_win[t] : -2;
        if (t < TOUT) {
            float* obase = out + ((size_t)b * 32 * (NSPAT * NSPAT) + bx) * TOUT + t;
#pragma unroll 1
            for (int oc = 0; oc < 32; ++oc)
                obase[(size_t)oc * (NSPAT * NSPAT) * TOUT] = (wv == oc) ? 1.f : 0.f;
        }
    }
}

extern "C" void kernel_launch(void* const* d_in, const int* in_sizes, int n_in,
                              void* d_out, int out_size) {
    const float* spikes = (const float*)d_in[0];
    const float* weight = (const float*)d_in[1];
    if (n_in >= 2 && in_sizes[0] == 576) {     // defensive input identification
        spikes = (const float*)d_in[1];
        weight = (const float*)d_in[0];
    }

    evt_precompute<<<3, 192>>>(weight);

    dim3 grid(NSPAT * NSPAT, 16);   // (n, batch)
    wta_kernel<<<grid, 32>>>(spikes, (float*)d_out);
}

// round 6
// speedup vs baseline: 2.7232x; 1.4172x over previous
#include <cuda_runtime.h>
#include <cstdint>
#include <cstddef>

// ---------------------------------------------------------------------------
// Spiking conv + WTA, Round 6: delta^2 event scatter with time-split grid
// reuse (2 halves of 76 rows through one 9.7KB buffer), direct bitmask
// scatter (no spike list), ballot-gated WTA.
// One 32-thread CTA per (b,ox,oy); lane = output channel.
//   r(tau) = tau/16 - (3/32) relu(tau-16w) + (1/32) relu(tau-48w)   (exact)
// ---------------------------------------------------------------------------

#define COUT   32
#define W18    18
#define KS     48
#define TIN    100
#define TOUT   149
#define NSPAT  31
#define THETA  5.4f
#define HROWS  76          // rows per half

// event tables, layout [w][o]
__device__ float4 g_t1[W18 * COUT];   // ev1a, ev1b, ev2a, ev2b
__device__ int    g_t2[W18 * COUT];   // n1 | (n2<<16)

__global__ void evt_precompute(const float* __restrict__ weight) {
    int idx = blockIdx.x * blockDim.x + threadIdx.x;
    if (idx >= W18 * COUT) return;
    int o = idx & 31;
    int w = idx >> 5;
    double wv = (double)weight[o * W18 + w];

    double p1 = 16.0 * wv;                    // peak knot
    int    n1 = (int)floor(p1) + 1;
    double f1 = (double)n1 - p1;              // in (0,1]
    const double c1 = -3.0 / 32.0;
    double p2 = 48.0 * wv;                    // zero-cross knot
    int    n2 = (int)floor(p2) + 1;
    double f2 = (double)n2 - p2;
    const double c2 = 1.0 / 32.0;

    g_t1[idx] = make_float4((float)(c1 * f1), (float)(c1 * (1.0 - f1)),
                            (float)(c2 * f2), (float)(c2 * (1.0 - f2)));
    g_t2[idx] = n1 | (n2 << 16);
}

// Neumaier compensated add: s += v, compensation c
__device__ __forceinline__ void kadd(float& s, float& c, float v) {
    float t = s + v;
    float e = (fabsf(s) >= fabsf(v)) ? ((s - t) + v) : ((v - t) + s);
    c += e;
    s = t;
}

__global__ __launch_bounds__(32)
void wta_kernel(const float* __restrict__ xin, float* __restrict__ out) {
    __shared__ float4   s_grid4[HROWS * COUT / 4];   // 9728 B, reused per half
    __shared__ float    s_cnt[152];                  // ramp d2 (count/16)
    __shared__ unsigned s_bits[72];                  // 18 rows x 4 t-words
    __shared__ int      s_win[152];                  // winner per t, -1 none

    float* s_grid = (float*)s_grid4;

    const int lane = threadIdx.x;
    const int bx   = blockIdx.x;                     // n = ox*31 + oy
    const int b    = blockIdx.y;
    const int ox   = bx / NSPAT;
    const int oy   = bx - ox * NSPAT;

    // ---- init cnt / win ----
#pragma unroll
    for (int i = lane; i < 152; i += 32) { s_cnt[i] = 0.f; s_win[i] = -1; }

    // ---- stage 1: spike bitmasks (72 = 18 rows x 4 t-segments) ----
    float vbuf[24];
#pragma unroll
    for (int batch = 0; batch < 3; ++batch) {
#pragma unroll
        for (int j = 0; j < 24; ++j) {
            int task = batch * 24 + j;
            int w = task >> 2, seg = task & 3;
            int i = w / 9, rem = w - i * 9, kx = rem / 3, ky = rem - kx * 3;
            int t = seg * 32 + lane;
            const float* row = xin +
                ((((size_t)b * 2 + i) * 64 + (2 * ox + kx)) * 64 + (2 * oy + ky)) * TIN;
            vbuf[j] = (t < TIN) ? __ldg(row + t) : 0.f;
        }
#pragma unroll
        for (int j = 0; j < 24; ++j) {
            unsigned m = __ballot_sync(0xffffffffu, vbuf[j] != 0.f);
            if (lane == 0) s_bits[batch * 24 + j] = m;
        }
    }
    __syncwarp();

    // ---- stage 1b: shared-ramp counts: cnt[s+2] = (#spikes at s)/16 ----
#pragma unroll
    for (int seg = 0; seg < 4; ++seg) {
        int c = 0;
#pragma unroll
        for (int w = 0; w < 18; ++w) c += (int)((s_bits[w * 4 + seg] >> lane) & 1u);
        int s = seg * 32 + lane;
        if (s < TIN) s_cnt[s + 2] = (float)c * 0.0625f;
    }
    __syncwarp();

    // ---- per-half: zero grid, scatter events, cumsum + WTA ----
    float* col = s_grid + lane;
    float a1 = 0.f, c1 = 0.f, a2 = 0.f;
    int dep = 0;

#pragma unroll 1
    for (int h = 0; h < 2; ++h) {
        const int lo = h * HROWS;

        // zero half grid
        {
            float4 z4 = make_float4(0.f, 0.f, 0.f, 0.f);
#pragma unroll
            for (int i = lane; i < HROWS * COUT / 4; i += 32) s_grid4[i] = z4;
        }
        __syncwarp();

        // per-seg spike filter: half0 needs s<=73, half1 needs s>=25
        unsigned segmask[4];
        if (h == 0) {
            segmask[0] = 0xffffffffu; segmask[1] = 0xffffffffu;
            segmask[2] = 0x000003ffu; segmask[3] = 0u;          // s<=73
        } else {
            segmask[0] = 0xfe000000u;                           // s>=25
            segmask[1] = 0xffffffffu; segmask[2] = 0xffffffffu;
            segmask[3] = 0xffffffffu;
        }

        // scatter hinge events (lane-private smem column, deterministic order)
#pragma unroll 1
        for (int w = 0; w < W18; ++w) {
            float4 ev = __ldg(&g_t1[w * 32 + lane]);
            int    nn = __ldg(&g_t2[w * 32 + lane]);
            int n1 = nn & 0xffff;
            int n2 = nn >> 16;
#pragma unroll
            for (int seg = 0; seg < 4; ++seg) {
                unsigned m = s_bits[w * 4 + seg] & segmask[seg];
                int sbase = seg * 32 + 1 - lo;       // r - lo for bit 0
                while (m) {
                    int bp = __ffs((int)m) - 1;
                    m &= m - 1;
                    int r1 = sbase + bp + n1;        // rel row of hinge-1 ev A
                    int r2 = sbase + bp + n2;        // rel row of hinge-2 ev A
                    if ((unsigned)r1 < (unsigned)HROWS)       col[r1 * 32]       += ev.x;
                    if ((unsigned)(r1 + 1) < (unsigned)HROWS) col[(r1 + 1) * 32] += ev.y;
                    if ((unsigned)r2 < (unsigned)HROWS)       col[r2 * 32]       += ev.z;
                    if ((unsigned)(r2 + 1) < (unsigned)HROWS) col[(r2 + 1) * 32] += ev.w;
                }
            }
        }
        __syncwarp();

        // double cumsum + ballot-gated WTA over this half's t range
        const int tend = (h == 0) ? HROWS : TOUT;
#pragma unroll 1
        for (int t = lo; t < tend; ++t) {
            float v = s_grid[(t - lo) * 32 + lane] + s_cnt[t];
            kadd(a1, c1, v);
            a2 += (a1 + c1);
            if (dep == 0) {
                unsigned fm = __ballot_sync(0xffffffffu, a2 > THETA);
                if (fm) {
                    float bv = a2; int bi = lane;
#pragma unroll
                    for (int off = 16; off; off >>= 1) {
                        float ov = __shfl_xor_sync(0xffffffffu, bv, off);
                        int   oi = __shfl_xor_sync(0xffffffffu, bi, off);
                        if (ov > bv || (ov == bv && oi < bi)) { bv = ov; bi = oi; }
                    }
                    if (lane == 0) s_win[t] = bi;
                    dep = 48;
                }
            }
            dep = dep > 0 ? dep - 1 : 0;
        }
        __syncwarp();
    }

    // ---- output: every element written, coalesced per channel row ----
#pragma unroll
    for (int q = 0; q < 5; ++q) {
        int t = q * 32 + lane;
        if (t < TOUT) {
            int wv = s_win[t];
            float* obase = out + ((size_t)b * 32 * (NSPAT * NSPAT) + bx) * TOUT + t;
#pragma unroll 1
            for (int oc = 0; oc < 32; ++oc)
                obase[(size_t)oc * (NSPAT * NSPAT) * TOUT] = (wv == oc) ? 1.f : 0.f;
        }
    }
}

extern "C" void kernel_launch(void* const* d_in, const int* in_sizes, int n_in,
                              void* d_out, int out_size) {
    const float* spikes = (const float*)d_in[0];
    const float* weight = (const float*)d_in[1];
    if (n_in >= 2 && in_sizes[0] == 576) {     // defensive input identification
        spikes = (const float*)d_in[1];
        weight = (const float*)d_in[0];
    }

    evt_precompute<<<3, 192>>>(weight);

    dim3 grid(NSPAT * NSPAT, 16);   // (n, batch)
    wta_kernel<<<grid, 32>>>(spikes, (float*)d_out);
}